// round 4
// baseline (speedup 1.0000x reference)
#include <cuda_runtime.h>
#include <cstdint>

// Problem: WindowAttention. b=32, n=4096 (64x64), c=512, WS=4, HEADS=8, hs=64.
// Window-ordered row index m = ((bi*16 + i)*16 + j)*16 + t maps to
// x row  grow = bi*4096 + (i*4 + t/4)*64 + (j*4 + t%4).
// Reference output is window-ordered -> final GEMM writes d_out contiguously.
//
// Round-4 structure (still blind; broker has yet to grant a GB300 hold):
//   pack_w:    Wq|Wk|Wv -> g_w[512][1536], bq|bk|bv -> g_b[1536]
//   gemm_tf32: x(permuted rows) @ g_w -> g_qkv[m][1536]   (one fused launch)
//   window_attn: per-window sigmoid attention on interleaved QKV
//   gemm_tf32: g_ctx @ Wo -> d_out (contiguous)

#define M_TOTAL 131072
#define KDIM 512
#define N_QKV 1536
#define N_OUT 512

// Scratch: static device arrays (allocation in kernel_launch is forbidden).
__device__ float g_qkv[201326592];   // 131072 x 1536  (768 MiB)
__device__ float g_ctx[67108864];    // 131072 x 512   (256 MiB)
__device__ float g_w[786432];        // 512 x 1536 packed weights
__device__ float g_b[1536];          // packed bias

__device__ __forceinline__ unsigned f2tf32(float f) {
    unsigned r;
    asm("cvt.rna.tf32.f32 %0, %1;" : "=r"(r) : "f"(f));
    return r;
}

// ---------------------------------------------------------------------------
// Pack Wq|Wk|Wv column-blocks into g_w ([k][1536]) and biases into g_b.
// ---------------------------------------------------------------------------
__global__ void pack_w(const float* __restrict__ Wq, const float* __restrict__ Wk,
                       const float* __restrict__ Wv, const float* __restrict__ bq,
                       const float* __restrict__ bk, const float* __restrict__ bv)
{
    const int idx = blockIdx.x * blockDim.x + threadIdx.x;  // 0 .. 512*512-1
    const int k = idx >> 9;
    const int n = idx & 511;
    g_w[(size_t)k * 1536 + n]        = Wq[idx];
    g_w[(size_t)k * 1536 + 512 + n]  = Wk[idx];
    g_w[(size_t)k * 1536 + 1024 + n] = Wv[idx];
    if (idx < 512) {
        g_b[idx]        = bq[idx];
        g_b[512 + idx]  = bk[idx];
        g_b[1024 + idx] = bv[idx];
    }
}

// ---------------------------------------------------------------------------
// TF32 GEMM: out[m][n] = sum_k A[rowmap(m)][k] * W[k][n] + bias[n]
// Block tile 128x128, BK=32, 256 threads = 8 warps (2 x 4), warp tile 64x32.
// 2-stage smem double buffer + register prefetch: one __syncthreads per K-tile.
// ldw / ldo parameterize the B/out row strides (1536 fused, 512 for O-GEMM).
// mma.sync.aligned.m16n8k8.row.col.f32.tf32.tf32.f32
// ---------------------------------------------------------------------------
#define BM 128
#define BN 128
#define BK 32
#define AS_STRIDE 36    // (row*36 + k): banks (4*row + k) % 32 -> conflict-free
#define BS_STRIDE 136   // (k*136 + n): banks (8*k + n) % 32  -> conflict-free

__global__ __launch_bounds__(256, 2)
void gemm_tf32(const float* __restrict__ A, const float* __restrict__ W,
               const float* __restrict__ bias, float* __restrict__ out,
               int ldw, int permute)
{
    __shared__ float As[2][BM][AS_STRIDE];   // [buf][m][k]
    __shared__ float Bs[2][BK][BS_STRIDE];   // [buf][k][n]

    const int tid   = threadIdx.x;
    const int lane  = tid & 31;
    const int warp  = tid >> 5;
    const int warpM = warp >> 2;          // 0..1
    const int warpN = warp & 3;           // 0..3
    const int grp   = lane >> 2;          // 0..7
    const int tig   = lane & 3;           // 0..3

    const int blockN = blockIdx.x * BN;
    const int blockM = blockIdx.y * BM;

    // A loader: each thread owns half of one row (16 floats).
    const int aRow = tid >> 1;             // 0..127
    const int aK0  = (tid & 1) * 16;       // 0 or 16
    int m = blockM + aRow;
    int grow;
    if (permute) {
        const int t   = m & 15;
        const int win = m >> 4;
        const int j   = win & 15;
        const int i   = (win >> 4) & 15;
        const int bi  = win >> 8;
        grow = bi * 4096 + (i * 4 + (t >> 2)) * 64 + (j * 4 + (t & 3));
    } else {
        grow = m;
    }
    const float* aPtr = A + (size_t)grow * KDIM;

    // B loader: thread loads 16 consecutive floats of one k-row.
    const int bK  = tid >> 3;              // 0..31
    const int bN0 = (tid & 7) * 16;        // 0..112
    const float* wPtr = W + (size_t)bK * ldw + blockN + bN0;

    float4 aReg[4], bReg[4];

    // ---- prologue: load tile 0 into registers ----
    #pragma unroll
    for (int i4 = 0; i4 < 4; i4++) {
        aReg[i4] = *reinterpret_cast<const float4*>(aPtr + aK0 + i4 * 4);
        bReg[i4] = *reinterpret_cast<const float4*>(wPtr + i4 * 4);
    }

    float acc[4][4][4];
    #pragma unroll
    for (int mt = 0; mt < 4; mt++)
        #pragma unroll
        for (int nt = 0; nt < 4; nt++)
            #pragma unroll
            for (int e = 0; e < 4; e++) acc[mt][nt][e] = 0.f;

    // store helper (tf32 conversion at smem-store time)
    auto storeTile = [&](int buf) {
        #pragma unroll
        for (int i4 = 0; i4 < 4; i4++) {
            float4 v = aReg[i4];
            v.x = __uint_as_float(f2tf32(v.x));
            v.y = __uint_as_float(f2tf32(v.y));
            v.z = __uint_as_float(f2tf32(v.z));
            v.w = __uint_as_float(f2tf32(v.w));
            *reinterpret_cast<float4*>(&As[buf][aRow][aK0 + i4 * 4]) = v;
            float4 u = bReg[i4];
            u.x = __uint_as_float(f2tf32(u.x));
            u.y = __uint_as_float(f2tf32(u.y));
            u.z = __uint_as_float(f2tf32(u.z));
            u.w = __uint_as_float(f2tf32(u.w));
            *reinterpret_cast<float4*>(&Bs[buf][bK][bN0 + i4 * 4]) = u;
        }
    };

    storeTile(0);
    __syncthreads();

    int buf = 0;
    for (int kt = 0; kt < KDIM; kt += BK) {
        const bool hasNext = (kt + BK) < KDIM;

        // ---- issue next tile's global loads early (hidden by MMAs) ----
        if (hasNext) {
            #pragma unroll
            for (int i4 = 0; i4 < 4; i4++) {
                aReg[i4] = *reinterpret_cast<const float4*>(aPtr + kt + BK + aK0 + i4 * 4);
                bReg[i4] = *reinterpret_cast<const float4*>(wPtr + (size_t)(kt + BK) * ldw + i4 * 4);
            }
        }

        // ---- compute on current buffer ----
        #pragma unroll
        for (int kk = 0; kk < BK; kk += 8) {
            unsigned afr[4][4];
            #pragma unroll
            for (int mt = 0; mt < 4; mt++) {
                const int r0 = warpM * 64 + mt * 16 + grp;
                afr[mt][0] = __float_as_uint(As[buf][r0    ][kk + tig    ]);
                afr[mt][1] = __float_as_uint(As[buf][r0 + 8][kk + tig    ]);
                afr[mt][2] = __float_as_uint(As[buf][r0    ][kk + tig + 4]);
                afr[mt][3] = __float_as_uint(As[buf][r0 + 8][kk + tig + 4]);
            }
            unsigned bfr[4][2];
            #pragma unroll
            for (int nt = 0; nt < 4; nt++) {
                const int cN = warpN * 32 + nt * 8 + grp;
                bfr[nt][0] = __float_as_uint(Bs[buf][kk + tig    ][cN]);
                bfr[nt][1] = __float_as_uint(Bs[buf][kk + tig + 4][cN]);
            }
            #pragma unroll
            for (int mt = 0; mt < 4; mt++)
                #pragma unroll
                for (int nt = 0; nt < 4; nt++) {
                    asm volatile(
                        "mma.sync.aligned.m16n8k8.row.col.f32.tf32.tf32.f32 "
                        "{%0,%1,%2,%3}, {%4,%5,%6,%7}, {%8,%9}, {%0,%1,%2,%3};"
                        : "+f"(acc[mt][nt][0]), "+f"(acc[mt][nt][1]),
                          "+f"(acc[mt][nt][2]), "+f"(acc[mt][nt][3])
                        : "r"(afr[mt][0]), "r"(afr[mt][1]),
                          "r"(afr[mt][2]), "r"(afr[mt][3]),
                          "r"(bfr[nt][0]), "r"(bfr[nt][1]));
                }
        }

        // ---- publish next tile ----
        if (hasNext) {
            storeTile(buf ^ 1);
            __syncthreads();
            buf ^= 1;
        }
    }

    // Epilogue: c0/c1 at (row grp, col tig*2 / +1); c2/c3 at row grp+8.
    #pragma unroll
    for (int mt = 0; mt < 4; mt++) {
        const int r0 = blockM + warpM * 64 + mt * 16 + grp;
        #pragma unroll
        for (int nt = 0; nt < 4; nt++) {
            const int c0 = blockN + warpN * 32 + nt * 8 + tig * 2;
            const float b0 = bias[c0];
            const float b1 = bias[c0 + 1];
            *reinterpret_cast<float2*>(&out[(size_t)r0 * ldw + c0]) =
                make_float2(acc[mt][nt][0] + b0, acc[mt][nt][1] + b1);
            *reinterpret_cast<float2*>(&out[(size_t)(r0 + 8) * ldw + c0]) =
                make_float2(acc[mt][nt][2] + b0, acc[mt][nt][3] + b1);
        }
    }
}

// ---------------------------------------------------------------------------
// Per-window sigmoid attention. One block per window (8192 blocks, 256 thr).
// QKV interleaved [m][1536]: Q at col 0, K at 512, V at 1024; head = 64-col
// chunk. Thread (r,u), tid=r*16+u: row r's 16 threads are lanes (r&1)*16.. of
// ONE warp -> probs via shfl (no smem/barrier). Double-buffered tiles +
// register prefetch of next head -> 1 __syncthreads per head.
// ---------------------------------------------------------------------------
__global__ __launch_bounds__(256)
void window_attn(const float* __restrict__ qkv, float* __restrict__ ctx)
{
    __shared__ float sq[2][16][68], sk[2][16][68], sv[2][16][68];

    const int tid = threadIdx.x;
    const int win = blockIdx.x;
    const int r   = tid >> 4;          // token row 0..15
    const int u   = tid & 15;          // token col 0..15
    const int c4  = u * 4;             // 0..60
    const int srcBase = (r & 1) * 16;  // lane base of row r's group within warp
    const size_t inBase  = ((size_t)win * 16 + r) * 1536;
    const size_t outBase = ((size_t)win * 16 + r) * 512;

    float4 aq, ak, av;
    {   // prefetch head 0
        aq = *reinterpret_cast<const float4*>(qkv + inBase + c4);
        ak = *reinterpret_cast<const float4*>(qkv + inBase + 512 + c4);
        av = *reinterpret_cast<const float4*>(qkv + inBase + 1024 + c4);
    }

    #pragma unroll
    for (int head = 0; head < 8; head++) {
        const int buf = head & 1;
        *reinterpret_cast<float4*>(&sq[buf][r][c4]) = aq;
        *reinterpret_cast<float4*>(&sk[buf][r][c4]) = ak;
        *reinterpret_cast<float4*>(&sv[buf][r][c4]) = av;
        __syncthreads();

        if (head < 7) {   // prefetch next head (hidden by dot products)
            const size_t off = inBase + (head + 1) * 64 + c4;
            aq = *reinterpret_cast<const float4*>(qkv + off);
            ak = *reinterpret_cast<const float4*>(qkv + off + 512);
            av = *reinterpret_cast<const float4*>(qkv + off + 1024);
        }

        // score s[r][u] = q_r . k_u / 8, then sigmoid
        float s = 0.f;
        #pragma unroll
        for (int d = 0; d < 64; d += 4) {
            float4 qa = *reinterpret_cast<const float4*>(&sq[buf][r][d]);
            float4 kb = *reinterpret_cast<const float4*>(&sk[buf][u][d]);
            s += qa.x * kb.x + qa.y * kb.y + qa.z * kb.z + qa.w * kb.w;
        }
        const float pMine = 1.f / (1.f + __expf(-0.125f * s));

        // ctx[r][c4..c4+3] = sum_uu p[r][uu] * v[uu][c4..]
        float4 o = make_float4(0.f, 0.f, 0.f, 0.f);
        #pragma unroll
        for (int uu = 0; uu < 16; uu++) {
            const float p = __shfl_sync(0xFFFFFFFFu, pMine, srcBase + uu);
            const float4 vv = *reinterpret_cast<const float4*>(&sv[buf][uu][c4]);
            o.x += p * vv.x; o.y += p * vv.y; o.z += p * vv.z; o.w += p * vv.w;
        }
        *reinterpret_cast<float4*>(ctx + outBase + head * 64 + c4) = o;
    }
}

// ---------------------------------------------------------------------------
extern "C" void kernel_launch(void* const* d_in, const int* in_sizes, int n_in,
                              void* d_out, int out_size) {
    const float* x  = (const float*)d_in[0];
    const float* Wq = (const float*)d_in[1];
    const float* bq = (const float*)d_in[2];
    const float* Wk = (const float*)d_in[3];
    const float* bk = (const float*)d_in[4];
    const float* Wv = (const float*)d_in[5];
    const float* bv = (const float*)d_in[6];
    const float* Wo = (const float*)d_in[7];
    const float* bo = (const float*)d_in[8];
    float* out = (float*)d_out;

    float *dqkv, *dc, *dw, *db;
    cudaGetSymbolAddress((void**)&dqkv, g_qkv);
    cudaGetSymbolAddress((void**)&dc,   g_ctx);
    cudaGetSymbolAddress((void**)&dw,   g_w);
    cudaGetSymbolAddress((void**)&db,   g_b);

    pack_w<<<512, 512>>>(Wq, Wk, Wv, bq, bk, bv);

    const dim3 blk(256);
    gemm_tf32<<<dim3(N_QKV / BN, M_TOTAL / BM), blk>>>(x, dw, db, dqkv, N_QKV, 1);
    window_attn<<<8192, 256>>>(dqkv, dc);
    gemm_tf32<<<dim3(N_OUT / BN, M_TOTAL / BM), blk>>>(dc, Wo, bo, out, N_OUT, 0);
}

// round 15
// speedup vs baseline: 1.0239x; 1.0239x over previous
#include <cuda_runtime.h>
#include <cstdint>

// WindowAttention: b=32, n=4096 (64x64), c=512, WS=4, HEADS=8, hs=64.
// Round 15 = unchanged resubmission of the audited round-10 kernel (six
// broker timeouts on this artifact; never measured). tcgen05 unavailable
// (harness targets sm_103 without 'a'). Response to round-4 ncu (L1=86.4%
// bound, tensor=34%):
//   * warp tile 64x64 (fragment bytes/MAC 0.1875 -> 0.125)
//   * cp.async.cg fills (single-pass, no staging regs)
//   * tf32 rounding off the GEMM path (round_x / pack_w / attn epilogue)
//   * Bs row stride 264 (256 + 8 pad): fill coverage exact, frag loads
//     conflict-free (banks tig*8+grp mod 32).

#define M_TOTAL 131072
#define KD 512

__device__ float g_qkv[201326592];   // 131072 x 1536
__device__ float g_ctx[67108864];    // 131072 x 512
__device__ float g_xr[67108864];     // 131072 x 512 (rounded x)
__device__ float g_w[786432];        // 512 x 1536 (N-major, rounded)
__device__ float g_wo[262144];       // 512 x 512  (N-major, rounded)
__device__ float g_b[1536];          // packed qkv bias

__device__ __forceinline__ uint32_t smem_u32(const void* p) {
    uint32_t a;
    asm("{ .reg .u64 t; cvta.to.shared.u64 t, %1; cvt.u32.u64 %0, t; }" : "=r"(a) : "l"(p));
    return a;
}
__device__ __forceinline__ unsigned f2tf32(float f) {
    unsigned r;
    asm("cvt.rna.tf32.f32 %0, %1;" : "=r"(r) : "f"(f));
    return r;
}
__device__ __forceinline__ float rtf(float f) { return __uint_as_float(f2tf32(f)); }

#define CPA16(dst, src) asm volatile("cp.async.cg.shared.global [%0], [%1], 16;" :: "r"(dst), "l"(src))
#define CPA_COMMIT()    asm volatile("cp.async.commit_group;" ::: "memory")
#define CPA_WAIT0()     asm volatile("cp.async.wait_group 0;" ::: "memory")
#define CPA_WAIT1()     asm volatile("cp.async.wait_group 1;" ::: "memory")

// ---------------------------------------------------------------------------
// pack_w: round weights to tf32 (N-major, input layout); pack biases.
// ---------------------------------------------------------------------------
__global__ void pack_w(const float* __restrict__ Wq, const float* __restrict__ Wk,
                       const float* __restrict__ Wv, const float* __restrict__ Wo,
                       const float* __restrict__ bq, const float* __restrict__ bk,
                       const float* __restrict__ bv)
{
    const int idx = blockIdx.x * blockDim.x + threadIdx.x;  // 0..262143
    const int k = idx >> 9;
    const int n = idx & 511;
    g_w[(size_t)k * 1536 + n]         = rtf(Wq[idx]);
    g_w[(size_t)k * 1536 + 512 + n]   = rtf(Wk[idx]);
    g_w[(size_t)k * 1536 + 1024 + n]  = rtf(Wv[idx]);
    g_wo[(size_t)k * 512 + n]         = rtf(Wo[idx]);
    if (idx < 512) {
        g_b[idx]        = bq[idx];
        g_b[512 + idx]  = bk[idx];
        g_b[1024 + idx] = bv[idx];
    }
}

// round_x: tf32-round activations once (removes cvt from GEMM fill path)
__global__ void round_x(const float* __restrict__ x)
{
    const int idx = blockIdx.x * blockDim.x + threadIdx.x;  // float4 index
    float4 v = reinterpret_cast<const float4*>(x)[idx];
    v.x = rtf(v.x); v.y = rtf(v.y); v.z = rtf(v.z); v.w = rtf(v.w);
    reinterpret_cast<float4*>(g_xr)[idx] = v;
}

// ---------------------------------------------------------------------------
// TF32 GEMM, mma.sync m16n8k8. Block 128x256, BK=32, 256 threads = 8 warps
// (2x4), warp tile 64x64 (acc 128 regs). cp.async.cg double-buffered fills.
// smem: As[2][128][36] = 36864 B, Bs[2][32][264] = 67584 B, total 104448 B.
// ---------------------------------------------------------------------------
#define BS_STRIDE 264
#define SM_GEMM 104448

__global__ __launch_bounds__(256, 1)
void gemm_tf32(const float* __restrict__ A, const float* __restrict__ W,
               const float* __restrict__ bias, float* __restrict__ out,
               int ldn, int permute)
{
    extern __shared__ float smf[];
    const uint32_t sb = smem_u32(smf);

    const int tid   = threadIdx.x;
    const int lane  = tid & 31;
    const int warp  = tid >> 5;
    const int warpM = warp >> 2;          // 0..1 -> 64-row half
    const int warpN = warp & 3;           // 0..3 -> 64-col quarter
    const int grp   = lane >> 2;          // 0..7
    const int tig   = lane & 3;           // 0..3

    const int blockN = blockIdx.x * 256;
    const int blockM = blockIdx.y * 128;

    // A fill: thread -> row tid>>1, 16 floats at (tid&1)*16 (4 x 16B chunks).
    const int aRow = tid >> 1;
    const int aK0  = (tid & 1) * 16;
    int m = blockM + aRow;
    int grow;
    if (permute) {
        const int t   = m & 15;
        const int win = m >> 4;
        const int j   = win & 15;
        const int i   = (win >> 4) & 15;
        const int bi  = win >> 8;
        grow = bi * 4096 + (i * 4 + (t >> 2)) * 64 + (j * 4 + (t & 3));
    } else {
        grow = m;
    }
    const float* aSrc = A + (size_t)grow * KD + aK0;
    const uint32_t aDst0 = sb + (uint32_t)(aRow * 36 + aK0) * 4;

    // B fill: thread -> k-row tid>>3, 32 floats at (tid&7)*32 (8 x 16B chunks).
    const int bK  = tid >> 3;
    const int bN0 = (tid & 7) * 32;
    const float* bSrc = W + (size_t)bK * ldn + blockN + bN0;
    const uint32_t bDst0 = sb + 36864u + (uint32_t)(bK * BS_STRIDE + bN0) * 4;

    auto issueTile = [&](int kt) {
        const int buf = kt & 1;
        const float* ap = aSrc + kt * 32;
        const uint32_t ad = aDst0 + buf * 18432u;             // 128*36*4
        #pragma unroll
        for (int c = 0; c < 4; c++) CPA16(ad + 16u * c, ap + 4 * c);
        const float* bp = bSrc + (size_t)kt * 32 * ldn;
        const uint32_t bd = bDst0 + buf * 33792u;             // 32*264*4
        #pragma unroll
        for (int c = 0; c < 8; c++) CPA16(bd + 16u * c, bp + 4 * c);
        CPA_COMMIT();
    };

    float acc[4][8][4];
    #pragma unroll
    for (int mt = 0; mt < 4; mt++)
        #pragma unroll
        for (int nt = 0; nt < 8; nt++)
            #pragma unroll
            for (int e = 0; e < 4; e++) acc[mt][nt][e] = 0.f;

    issueTile(0);
    issueTile(1);

    for (int kt = 0; kt < 16; kt++) {
        if (kt < 15) { CPA_WAIT1(); } else { CPA_WAIT0(); }
        __syncthreads();

        const float* As_ = smf + (kt & 1) * 4608;              // [row*36 + k]
        const float* Bs_ = smf + 9216 + (kt & 1) * 8448;       // [k*264 + n]

        #pragma unroll
        for (int kk = 0; kk < 32; kk += 8) {
            unsigned afr[4][4];
            #pragma unroll
            for (int mt = 0; mt < 4; mt++) {
                const int r0 = warpM * 64 + mt * 16 + grp;
                afr[mt][0] = __float_as_uint(As_[r0 * 36 + kk + tig]);
                afr[mt][1] = __float_as_uint(As_[(r0 + 8) * 36 + kk + tig]);
                afr[mt][2] = __float_as_uint(As_[r0 * 36 + kk + tig + 4]);
                afr[mt][3] = __float_as_uint(As_[(r0 + 8) * 36 + kk + tig + 4]);
            }
            #pragma unroll
            for (int nt = 0; nt < 8; nt++) {
                const int cN = warpN * 64 + nt * 8 + grp;
                const unsigned b0 = __float_as_uint(Bs_[(kk + tig) * BS_STRIDE + cN]);
                const unsigned b1 = __float_as_uint(Bs_[(kk + tig + 4) * BS_STRIDE + cN]);
                #pragma unroll
                for (int mt = 0; mt < 4; mt++) {
                    asm volatile(
                        "mma.sync.aligned.m16n8k8.row.col.f32.tf32.tf32.f32 "
                        "{%0,%1,%2,%3}, {%4,%5,%6,%7}, {%8,%9}, {%0,%1,%2,%3};"
                        : "+f"(acc[mt][nt][0]), "+f"(acc[mt][nt][1]),
                          "+f"(acc[mt][nt][2]), "+f"(acc[mt][nt][3])
                        : "r"(afr[mt][0]), "r"(afr[mt][1]),
                          "r"(afr[mt][2]), "r"(afr[mt][3]),
                          "r"(b0), "r"(b1));
                }
            }
        }

        __syncthreads();                 // all warps done reading this buffer
        if (kt + 2 < 16) issueTile(kt + 2);
    }

    // Epilogue: c0/c1 at (row grp, col tig*2/+1); c2/c3 at row grp+8.
    #pragma unroll
    for (int mt = 0; mt < 4; mt++) {
        const int r0 = blockM + warpM * 64 + mt * 16 + grp;
        #pragma unroll
        for (int nt = 0; nt < 8; nt++) {
            const int c0 = blockN + warpN * 64 + nt * 8 + tig * 2;
            const float b0 = bias[c0];
            const float b1 = bias[c0 + 1];
            *reinterpret_cast<float2*>(&out[(size_t)r0 * ldn + c0]) =
                make_float2(acc[mt][nt][0] + b0, acc[mt][nt][1] + b1);
            *reinterpret_cast<float2*>(&out[(size_t)(r0 + 8) * ldn + c0]) =
                make_float2(acc[mt][nt][2] + b0, acc[mt][nt][3] + b1);
        }
    }
}

// ---------------------------------------------------------------------------
// Per-window sigmoid attention (structure = passing round-4 kernel), writing
// tf32-rounded ctx so the O-GEMM fill is a raw copy.
// QKV interleaved [m][1536]: Q at 0, K at 512, V at 1024; head = 64-col chunk.
// ---------------------------------------------------------------------------
__global__ __launch_bounds__(256)
void window_attn(const float* __restrict__ qkv, float* __restrict__ ctx)
{
    __shared__ float sq[2][16][68], sk[2][16][68], sv[2][16][68];

    const int tid = threadIdx.x;
    const int win = blockIdx.x;
    const int r   = tid >> 4;
    const int u   = tid & 15;
    const int c4  = u * 4;
    const int srcBase = (r & 1) * 16;
    const size_t inBase  = ((size_t)win * 16 + r) * 1536;
    const size_t outBase = ((size_t)win * 16 + r) * 512;

    float4 aq, ak, av;
    aq = *reinterpret_cast<const float4*>(qkv + inBase + c4);
    ak = *reinterpret_cast<const float4*>(qkv + inBase + 512 + c4);
    av = *reinterpret_cast<const float4*>(qkv + inBase + 1024 + c4);

    #pragma unroll
    for (int head = 0; head < 8; head++) {
        const int buf = head & 1;
        *reinterpret_cast<float4*>(&sq[buf][r][c4]) = aq;
        *reinterpret_cast<float4*>(&sk[buf][r][c4]) = ak;
        *reinterpret_cast<float4*>(&sv[buf][r][c4]) = av;
        __syncthreads();

        if (head < 7) {
            const size_t off = inBase + (head + 1) * 64 + c4;
            aq = *reinterpret_cast<const float4*>(qkv + off);
            ak = *reinterpret_cast<const float4*>(qkv + off + 512);
            av = *reinterpret_cast<const float4*>(qkv + off + 1024);
        }

        float s = 0.f;
        #pragma unroll
        for (int d = 0; d < 64; d += 4) {
            float4 qa = *reinterpret_cast<const float4*>(&sq[buf][r][d]);
            float4 kb = *reinterpret_cast<const float4*>(&sk[buf][u][d]);
            s += qa.x * kb.x + qa.y * kb.y + qa.z * kb.z + qa.w * kb.w;
        }
        const float pMine = 1.f / (1.f + __expf(-0.125f * s));

        float4 o = make_float4(0.f, 0.f, 0.f, 0.f);
        #pragma unroll
        for (int uu = 0; uu < 16; uu++) {
            const float p = __shfl_sync(0xFFFFFFFFu, pMine, srcBase + uu);
            const float4 vv = *reinterpret_cast<const float4*>(&sv[buf][uu][c4]);
            o.x += p * vv.x; o.y += p * vv.y; o.z += p * vv.z; o.w += p * vv.w;
        }
        // tf32-round here (identical numerics to rounding at GEMM fill time)
        o.x = rtf(o.x); o.y = rtf(o.y); o.z = rtf(o.z); o.w = rtf(o.w);
        *reinterpret_cast<float4*>(ctx + outBase + head * 64 + c4) = o;
    }
}

// ---------------------------------------------------------------------------
extern "C" void kernel_launch(void* const* d_in, const int* in_sizes, int n_in,
                              void* d_out, int out_size) {
    const float* x  = (const float*)d_in[0];
    const float* Wq = (const float*)d_in[1];
    const float* bq = (const float*)d_in[2];
    const float* Wk = (const float*)d_in[3];
    const float* bk = (const float*)d_in[4];
    const float* Wv = (const float*)d_in[5];
    const float* bv = (const float*)d_in[6];
    const float* Wo = (const float*)d_in[7];
    const float* bo = (const float*)d_in[8];
    float* out = (float*)d_out;

    float *dqkv, *dc, *dxr, *dw, *dwo, *db;
    cudaGetSymbolAddress((void**)&dqkv, g_qkv);
    cudaGetSymbolAddress((void**)&dc,   g_ctx);
    cudaGetSymbolAddress((void**)&dxr,  g_xr);
    cudaGetSymbolAddress((void**)&dw,   g_w);
    cudaGetSymbolAddress((void**)&dwo,  g_wo);
    cudaGetSymbolAddress((void**)&db,   g_b);

    cudaFuncSetAttribute(gemm_tf32, cudaFuncAttributeMaxDynamicSharedMemorySize, SM_GEMM);

    pack_w<<<512, 512>>>(Wq, Wk, Wv, Wo, bq, bk, bv);
    round_x<<<16384, 1024>>>(x);
    gemm_tf32<<<dim3(6, 1024), 256, SM_GEMM>>>(dxr, dw, db, dqkv, 1536, 1);
    window_attn<<<8192, 256>>>(dqkv, dc);
    gemm_tf32<<<dim3(2, 1024), 256, SM_GEMM>>>(dc, dwo, bo, out, 512, 0);
}